// round 16
// baseline (speedup 1.0000x reference)
#include <cuda_runtime.h>
#include <cuda_fp16.h>

// HDTBLUT: 4 LUT kernels (h,d,t,b) x 4 rotations, 2x upscale, reflect pad.
// FINAL (champion, re-validated twice: wall 197.1-197.5us, kernel ~194us).
// Structure: nibble-packed window indexing; reversal-symmetry-merged fp16
// h/d tables (one 16B gather serves two pixels; hi-half routed via shfl /
// smem slots); fp16 t/b tables; frozen load-issue ordering (max MLP);
// __launch_bounds__(512,3). ~12.8 gathers/px vs 16 naive; L1tex gather
// wavefronts are the binding resource (~90% busy).

#define NN    1024
#define OW    2048
#define TX    32
#define TY    16
#define PR    6           // packed 64-bit pair entries per row (5 used + pad)
#define SROWS 22          // TY + 6
#define SLW   36          // slot array width

__device__ uint4 g_Hh[65536];
__device__ uint4 g_Dd[65536];
__device__ ulonglong1 g_Tt[65536];   // {h2(w0,w1), h2(w2,w3)}
__device__ ulonglong1 g_Bb[65536];

__device__ __forceinline__ void addx2(unsigned long long &a, unsigned long long b) {
    asm("add.rn.f32x2 %0, %0, %1;" : "+l"(a) : "l"(b));
}
__device__ __forceinline__ float lo32(unsigned long long s) {
    return __uint_as_float((unsigned int)s);
}
__device__ __forceinline__ float hi32(unsigned long long s) {
    return __uint_as_float((unsigned int)(s >> 32));
}
__device__ __host__ __forceinline__ unsigned rev16(unsigned w) {
    unsigned s = ((w & 0x0F0Fu) << 4) | ((w >> 4) & 0x0F0Fu);
    return ((s & 0xFFu) << 8) | (s >> 8);
}
__device__ __forceinline__ int refl(int c) {
    return c < 0 ? -c : (c >= NN ? 2 * NN - 2 - c : c);
}
__device__ __forceinline__ unsigned h2pack(float a, float b) {
    __half2 h = __floats2half2_rn(a, b);
    return *(unsigned*)&h;
}
// accumulate fp16x4 (two half2 words) into packed f32x2 accumulators
__device__ __forceinline__ void acc16(unsigned long long &sl, unsigned long long &sh,
                                      unsigned h2a, unsigned h2b) {
    float2 fa = __half22float2(*(__half2*)&h2a);
    float2 fb = __half22float2(*(__half2*)&h2b);
    unsigned long long pa, pb;
    asm("mov.b64 %0, {%1, %2};" : "=l"(pa) : "f"(fa.x), "f"(fa.y));
    asm("mov.b64 %0, {%1, %2};" : "=l"(pb) : "f"(fb.x), "f"(fb.y));
    addx2(sl, pa); addx2(sh, pb);
}

__global__ __launch_bounds__(256)
void prep_kernel(const float4* __restrict__ wh, const float4* __restrict__ wd,
                 const float4* __restrict__ wt, const float4* __restrict__ wb) {
    const int i = blockIdx.x * 256 + threadIdx.x;
    const int r = rev16(i);
    float4 f = __ldg(&wh[i]), g = __ldg(&wh[r]);
    g_Hh[i] = make_uint4(h2pack(f.x, f.y), h2pack(f.z, f.w),
                         h2pack(g.x, g.y), h2pack(g.z, g.w));
    f = __ldg(&wd[i]); g = __ldg(&wd[r]);
    g_Dd[i] = make_uint4(h2pack(f.x, f.y), h2pack(f.z, f.w),
                         h2pack(g.x, g.y), h2pack(g.z, g.w));
    f = __ldg(&wt[i]);
    g_Tt[i].x = ((unsigned long long)h2pack(f.z, f.w) << 32) | h2pack(f.x, f.y);
    f = __ldg(&wb[i]);
    g_Bb[i].x = ((unsigned long long)h2pack(f.z, f.w) << 32) | h2pack(f.x, f.y);
}

__global__ __launch_bounds__(512, 3)
void lut4_kernel(const int* __restrict__ img, float* __restrict__ out)
{
    __shared__ unsigned long long pk64[SROWS * PR];
    __shared__ uint2 sl[3][19][SLW];   // 0: vert(B), 1: diag(C), 2: anti(D)

    const int tx = threadIdx.x, ty = threadIdx.y;
    const int tid = ty * TX + tx;
    const int x0 = blockIdx.x * TX, y0 = blockIdx.y * TY;
    const int* ib = img + (size_t)blockIdx.z * (NN * NN);

    // Pack nibble rows straight from global (reflect at edges).
    if (tid < SROWS * 6) {
        const int row = tid / 6, w = tid - row * 6;
        const int gy = refl(y0 - 3 + row);
        const int gx0 = x0 - 8 + 8 * w;
        unsigned word;
        if (x0 >= 8 && x0 + 40 <= NN) {
            const int4* s = (const int4*)(ib + gy * NN + gx0);
            const int4 u0 = __ldg(s), u1 = __ldg(s + 1);
            word = ((unsigned)u0.x << 28) | ((unsigned)u0.y << 24) |
                   ((unsigned)u0.z << 20) | ((unsigned)u0.w << 16) |
                   ((unsigned)u1.x << 12) | ((unsigned)u1.y << 8)  |
                   ((unsigned)u1.z << 4)  |  (unsigned)u1.w;
        } else {
            word = 0;
            const int* rp = ib + gy * NN;
#pragma unroll
            for (int k = 0; k < 8; k++)
                word = (word << 4) | (unsigned)__ldg(rp + refl(gx0 + k));
        }
        unsigned* pw = (unsigned*)&pk64[row * PR];
        if (w < 5) pw[2 * w + 1] = word;
        if (w > 0) pw[2 * (w - 1)] = word;
    }
    __syncthreads();

    // 7x7 window rows as 32-bit regs; nibble j (j=0..6, center 3) at bits [28-4j,32-4j).
    unsigned H[7];
    const int base = tx + 5;
    const int w0 = base >> 3;
    const int sh = (base & 7) * 4;
#pragma unroll
    for (int r = 0; r < 7; r++) {
        const unsigned long long P = pk64[(ty + r) * PR + w0];
        H[r] = __funnelshift_l((unsigned)P, (unsigned)(P >> 32), sh);
    }

#define NIB(r, j) ((H[r] >> (28 - 4 * (j))) & 0xFu)

    // forward runs starting at p
    const unsigned hrun = (H[3] >> 4) & 0xFFFFu;                       // horiz
    const unsigned wl   = H[3] >> 16;                                  // horiz run at p-3 (fwd)
    const unsigned A12  = (wl & 0xFu) << 12;
    const unsigned vrun = A12 | (NIB(4,3) << 8) | (NIB(5,3) << 4) | NIB(6,3);
    const unsigned drun = A12 | (NIB(4,4) << 8) | (NIB(5,5) << 4) | NIB(6,6);
    const unsigned arun = A12 | (NIB(4,2) << 8) | (NIB(5,1) << 4) | NIB(6,0);
    // runs starting 3 back along each direction (for boundary fallbacks)
    const unsigned vrun3 = (NIB(0,3) << 12) | (NIB(1,3) << 8) | (NIB(2,3) << 4) | NIB(3,3);
    const unsigned drun3 = (NIB(0,0) << 12) | (NIB(1,1) << 8) | (NIB(2,2) << 4) | NIB(3,3);
    const unsigned arun3 = (NIB(0,6) << 12) | (NIB(1,5) << 8) | (NIB(2,4) << 4) | NIB(3,3);

    // t/b indices
    const unsigned iT0 = A12 | (NIB(5,4) << 8) | (NIB(6,4) << 4) | NIB(6,5);
    const unsigned iT1 = A12 | (NIB(4,1) << 8) | (NIB(4,0) << 4) | NIB(5,0);
    const unsigned iT2 = A12 | (NIB(1,2) << 8) | (NIB(0,2) << 4) | NIB(0,1);
    const unsigned iT3 = A12 | (NIB(2,5) << 8) | (NIB(2,6) << 4) | NIB(1,6);
    const unsigned iB0 = A12 | (NIB(4,5) << 8) | (NIB(4,6) << 4) | NIB(5,6);
    const unsigned iB1 = A12 | (NIB(5,2) << 8) | (NIB(6,2) << 4) | NIB(6,1);
    const unsigned iB2 = A12 | (NIB(2,1) << 8) | (NIB(2,0) << 4) | NIB(1,0);
    const unsigned iB3 = A12 | (NIB(1,4) << 8) | (NIB(0,4) << 4) | NIB(0,5);
#undef NIB

    unsigned long long s0l = 0, s0h = 0, s1l = 0, s1h = 0;
    unsigned long long s2l = 0, s2h = 0, s3l = 0, s3h = 0;

    // ── merged gathers (lo-half = own r0/r1; hi-half routed to run-end pixel)
    const uint4 gh = __ldg(&g_Hh[hrun]);
    const uint4 gv = __ldg(&g_Hh[vrun]);
    const uint4 gd = __ldg(&g_Dd[drun]);
    const uint4 ga = __ldg(&g_Dd[arun]);

    // boundary fallbacks (issue early so latency overlaps)
    uint2 fB = make_uint2(0, 0), fC = fB, fD = fB;
    if (ty < 3)            { uint4 t = __ldg(&g_Hh[vrun3]); fB = make_uint2(t.z, t.w); }
    if (ty < 3 || tx < 3)  { uint4 t = __ldg(&g_Dd[drun3]); fC = make_uint2(t.z, t.w); }
    if (ty < 3 || tx > 28) { uint4 t = __ldg(&g_Dd[arun3]); fD = make_uint2(t.z, t.w); }

    // t/b passes (fp16 tables), fully before the slot barrier
#define PASSH(W, I0, I1, I2, I3) { unsigned long long e; \
    e = __ldg(&W[I0].x); acc16(s0l, s0h, (unsigned)e, (unsigned)(e >> 32)); \
    e = __ldg(&W[I1].x); acc16(s1l, s1h, (unsigned)e, (unsigned)(e >> 32)); \
    e = __ldg(&W[I2].x); acc16(s2l, s2h, (unsigned)e, (unsigned)(e >> 32)); \
    e = __ldg(&W[I3].x); acc16(s3l, s3h, (unsigned)e, (unsigned)(e >> 32)); }
    PASSH(g_Tt, iT0, iT1, iT2, iT3)
    PASSH(g_Bb, iB0, iB1, iB2, iB3)
#undef PASSH

    // horizontal hi-half via shuffle: pixel p's r2 comes from lane tx-3
    unsigned a0 = __shfl_up_sync(0xFFFFFFFFu, gh.z, 3);
    unsigned a1 = __shfl_up_sync(0xFFFFFFFFu, gh.w, 3);
    if (tx < 3) { const uint4 t = __ldg(&g_Hh[wl]); a0 = t.z; a1 = t.w; }

    // slot writes: dest pixel coords
    sl[0][ty + 3][tx]     = make_uint2(gv.z, gv.w);   // vert  -> (ty+3, tx)
    sl[1][ty + 3][tx + 3] = make_uint2(gd.z, gd.w);   // diag  -> (ty+3, tx+3)
    sl[2][ty + 3][tx]     = make_uint2(ga.z, ga.w);   // anti  -> (ty+3, tx-3), x stored +3
    __syncthreads();

    const uint2 rB0 = sl[0][ty][tx];
    const uint2 rC0 = sl[1][ty][tx];
    const uint2 rD0 = sl[2][ty][tx + 3];
    const uint2 rB = (ty >= 3)             ? rB0 : fB;
    const uint2 rC = (ty >= 3 && tx >= 3)  ? rC0 : fC;
    const uint2 rD = (ty >= 3 && tx <= 28) ? rD0 : fD;

    // accumulate merged (fp16) contributions
    acc16(s0l, s0h, gh.x, gh.y);   // h r0
    acc16(s1l, s1h, gv.x, gv.y);   // h r1
    acc16(s2l, s2h, a0,   a1);     // h r2
    acc16(s3l, s3h, rB.x, rB.y);   // h r3
    acc16(s0l, s0h, gd.x, gd.y);   // d r0
    acc16(s1l, s1h, ga.x, ga.y);   // d r1
    acc16(s2l, s2h, rC.x, rC.y);   // d r2
    acc16(s3l, s3h, rD.x, rD.y);   // d r3

    const float S0x = lo32(s0l), S0y = hi32(s0l), S0z = lo32(s0h), S0w = hi32(s0h);
    const float S1x = lo32(s1l), S1y = hi32(s1l), S1z = lo32(s1h), S1w = hi32(s1h);
    const float S2x = lo32(s2l), S2y = hi32(s2l), S2z = lo32(s2h), S2w = hi32(s2h);
    const float S3x = lo32(s3l), S3y = hi32(s3l), S3z = lo32(s3h), S3w = hi32(s3h);

    const float a00 = (S0x + S1z + S2w + S3y) * 0.25f;
    const float a01 = (S0y + S1x + S2z + S3w) * 0.25f;
    const float a10 = (S0z + S1w + S2y + S3x) * 0.25f;
    const float a11 = (S0w + S1y + S2x + S3z) * 0.25f;

    float* ob = out + (size_t)blockIdx.z * ((size_t)OW * OW)
                    + (size_t)(2 * (y0 + ty)) * OW + 2 * (x0 + tx);
    *(float2*)(ob)      = make_float2(a00, a01);
    *(float2*)(ob + OW) = make_float2(a10, a11);
}

extern "C" void kernel_launch(void* const* d_in, const int* in_sizes, int n_in,
                              void* d_out, int out_size) {
    (void)n_in; (void)out_size;
    const int* img = (const int*)d_in[0];
    const int B = in_sizes[0] / (NN * NN);
    prep_kernel<<<256, 256>>>((const float4*)d_in[1], (const float4*)d_in[2],
                              (const float4*)d_in[3], (const float4*)d_in[4]);
    dim3 blk(TX, TY, 1);
    dim3 grd(NN / TX, NN / TY, B);
    lut4_kernel<<<grd, blk>>>(img, (float*)d_out);
}

// round 17
// speedup vs baseline: 1.0057x; 1.0057x over previous
#include <cuda_runtime.h>
#include <cuda_fp16.h>

// HDTBLUT: 4 LUT kernels (h,d,t,b) x 4 rotations, 2x upscale, reflect pad.
// R17 = champion (wall 197.1-198.8us, kernel 193.2-194.6us) with the two
// final output stores issued as st.global.cs (streaming / evict-first) so
// the 64MB write stream doesn't evict the 3MB L2-resident LUT tables.
// Everything before the stores is byte-identical to the frozen champion.

#define NN    1024
#define OW    2048
#define TX    32
#define TY    16
#define PR    6           // packed 64-bit pair entries per row (5 used + pad)
#define SROWS 22          // TY + 6
#define SLW   36          // slot array width

__device__ uint4 g_Hh[65536];
__device__ uint4 g_Dd[65536];
__device__ ulonglong1 g_Tt[65536];   // {h2(w0,w1), h2(w2,w3)}
__device__ ulonglong1 g_Bb[65536];

__device__ __forceinline__ void addx2(unsigned long long &a, unsigned long long b) {
    asm("add.rn.f32x2 %0, %0, %1;" : "+l"(a) : "l"(b));
}
__device__ __forceinline__ float lo32(unsigned long long s) {
    return __uint_as_float((unsigned int)s);
}
__device__ __forceinline__ float hi32(unsigned long long s) {
    return __uint_as_float((unsigned int)(s >> 32));
}
__device__ __host__ __forceinline__ unsigned rev16(unsigned w) {
    unsigned s = ((w & 0x0F0Fu) << 4) | ((w >> 4) & 0x0F0Fu);
    return ((s & 0xFFu) << 8) | (s >> 8);
}
__device__ __forceinline__ int refl(int c) {
    return c < 0 ? -c : (c >= NN ? 2 * NN - 2 - c : c);
}
__device__ __forceinline__ unsigned h2pack(float a, float b) {
    __half2 h = __floats2half2_rn(a, b);
    return *(unsigned*)&h;
}
// accumulate fp16x4 (two half2 words) into packed f32x2 accumulators
__device__ __forceinline__ void acc16(unsigned long long &sl, unsigned long long &sh,
                                      unsigned h2a, unsigned h2b) {
    float2 fa = __half22float2(*(__half2*)&h2a);
    float2 fb = __half22float2(*(__half2*)&h2b);
    unsigned long long pa, pb;
    asm("mov.b64 %0, {%1, %2};" : "=l"(pa) : "f"(fa.x), "f"(fa.y));
    asm("mov.b64 %0, {%1, %2};" : "=l"(pb) : "f"(fb.x), "f"(fb.y));
    addx2(sl, pa); addx2(sh, pb);
}
// streaming (evict-first) 8B store of two floats
__device__ __forceinline__ void stcs2(float* p, float a, float b) {
    asm volatile("st.global.cs.v2.f32 [%0], {%1, %2};" :: "l"(p), "f"(a), "f"(b) : "memory");
}

__global__ __launch_bounds__(256)
void prep_kernel(const float4* __restrict__ wh, const float4* __restrict__ wd,
                 const float4* __restrict__ wt, const float4* __restrict__ wb) {
    const int i = blockIdx.x * 256 + threadIdx.x;
    const int r = rev16(i);
    float4 f = __ldg(&wh[i]), g = __ldg(&wh[r]);
    g_Hh[i] = make_uint4(h2pack(f.x, f.y), h2pack(f.z, f.w),
                         h2pack(g.x, g.y), h2pack(g.z, g.w));
    f = __ldg(&wd[i]); g = __ldg(&wd[r]);
    g_Dd[i] = make_uint4(h2pack(f.x, f.y), h2pack(f.z, f.w),
                         h2pack(g.x, g.y), h2pack(g.z, g.w));
    f = __ldg(&wt[i]);
    g_Tt[i].x = ((unsigned long long)h2pack(f.z, f.w) << 32) | h2pack(f.x, f.y);
    f = __ldg(&wb[i]);
    g_Bb[i].x = ((unsigned long long)h2pack(f.z, f.w) << 32) | h2pack(f.x, f.y);
}

__global__ __launch_bounds__(512, 3)
void lut4_kernel(const int* __restrict__ img, float* __restrict__ out)
{
    __shared__ unsigned long long pk64[SROWS * PR];
    __shared__ uint2 sl[3][19][SLW];   // 0: vert(B), 1: diag(C), 2: anti(D)

    const int tx = threadIdx.x, ty = threadIdx.y;
    const int tid = ty * TX + tx;
    const int x0 = blockIdx.x * TX, y0 = blockIdx.y * TY;
    const int* ib = img + (size_t)blockIdx.z * (NN * NN);

    // Pack nibble rows straight from global (reflect at edges).
    if (tid < SROWS * 6) {
        const int row = tid / 6, w = tid - row * 6;
        const int gy = refl(y0 - 3 + row);
        const int gx0 = x0 - 8 + 8 * w;
        unsigned word;
        if (x0 >= 8 && x0 + 40 <= NN) {
            const int4* s = (const int4*)(ib + gy * NN + gx0);
            const int4 u0 = __ldg(s), u1 = __ldg(s + 1);
            word = ((unsigned)u0.x << 28) | ((unsigned)u0.y << 24) |
                   ((unsigned)u0.z << 20) | ((unsigned)u0.w << 16) |
                   ((unsigned)u1.x << 12) | ((unsigned)u1.y << 8)  |
                   ((unsigned)u1.z << 4)  |  (unsigned)u1.w;
        } else {
            word = 0;
            const int* rp = ib + gy * NN;
#pragma unroll
            for (int k = 0; k < 8; k++)
                word = (word << 4) | (unsigned)__ldg(rp + refl(gx0 + k));
        }
        unsigned* pw = (unsigned*)&pk64[row * PR];
        if (w < 5) pw[2 * w + 1] = word;
        if (w > 0) pw[2 * (w - 1)] = word;
    }
    __syncthreads();

    // 7x7 window rows as 32-bit regs; nibble j (j=0..6, center 3) at bits [28-4j,32-4j).
    unsigned H[7];
    const int base = tx + 5;
    const int w0 = base >> 3;
    const int sh = (base & 7) * 4;
#pragma unroll
    for (int r = 0; r < 7; r++) {
        const unsigned long long P = pk64[(ty + r) * PR + w0];
        H[r] = __funnelshift_l((unsigned)P, (unsigned)(P >> 32), sh);
    }

#define NIB(r, j) ((H[r] >> (28 - 4 * (j))) & 0xFu)

    // forward runs starting at p
    const unsigned hrun = (H[3] >> 4) & 0xFFFFu;                       // horiz
    const unsigned wl   = H[3] >> 16;                                  // horiz run at p-3 (fwd)
    const unsigned A12  = (wl & 0xFu) << 12;
    const unsigned vrun = A12 | (NIB(4,3) << 8) | (NIB(5,3) << 4) | NIB(6,3);
    const unsigned drun = A12 | (NIB(4,4) << 8) | (NIB(5,5) << 4) | NIB(6,6);
    const unsigned arun = A12 | (NIB(4,2) << 8) | (NIB(5,1) << 4) | NIB(6,0);
    // runs starting 3 back along each direction (for boundary fallbacks)
    const unsigned vrun3 = (NIB(0,3) << 12) | (NIB(1,3) << 8) | (NIB(2,3) << 4) | NIB(3,3);
    const unsigned drun3 = (NIB(0,0) << 12) | (NIB(1,1) << 8) | (NIB(2,2) << 4) | NIB(3,3);
    const unsigned arun3 = (NIB(0,6) << 12) | (NIB(1,5) << 8) | (NIB(2,4) << 4) | NIB(3,3);

    // t/b indices
    const unsigned iT0 = A12 | (NIB(5,4) << 8) | (NIB(6,4) << 4) | NIB(6,5);
    const unsigned iT1 = A12 | (NIB(4,1) << 8) | (NIB(4,0) << 4) | NIB(5,0);
    const unsigned iT2 = A12 | (NIB(1,2) << 8) | (NIB(0,2) << 4) | NIB(0,1);
    const unsigned iT3 = A12 | (NIB(2,5) << 8) | (NIB(2,6) << 4) | NIB(1,6);
    const unsigned iB0 = A12 | (NIB(4,5) << 8) | (NIB(4,6) << 4) | NIB(5,6);
    const unsigned iB1 = A12 | (NIB(5,2) << 8) | (NIB(6,2) << 4) | NIB(6,1);
    const unsigned iB2 = A12 | (NIB(2,1) << 8) | (NIB(2,0) << 4) | NIB(1,0);
    const unsigned iB3 = A12 | (NIB(1,4) << 8) | (NIB(0,4) << 4) | NIB(0,5);
#undef NIB

    unsigned long long s0l = 0, s0h = 0, s1l = 0, s1h = 0;
    unsigned long long s2l = 0, s2h = 0, s3l = 0, s3h = 0;

    // ── merged gathers (lo-half = own r0/r1; hi-half routed to run-end pixel)
    const uint4 gh = __ldg(&g_Hh[hrun]);
    const uint4 gv = __ldg(&g_Hh[vrun]);
    const uint4 gd = __ldg(&g_Dd[drun]);
    const uint4 ga = __ldg(&g_Dd[arun]);

    // boundary fallbacks (issue early so latency overlaps)
    uint2 fB = make_uint2(0, 0), fC = fB, fD = fB;
    if (ty < 3)            { uint4 t = __ldg(&g_Hh[vrun3]); fB = make_uint2(t.z, t.w); }
    if (ty < 3 || tx < 3)  { uint4 t = __ldg(&g_Dd[drun3]); fC = make_uint2(t.z, t.w); }
    if (ty < 3 || tx > 28) { uint4 t = __ldg(&g_Dd[arun3]); fD = make_uint2(t.z, t.w); }

    // t/b passes (fp16 tables), fully before the slot barrier
#define PASSH(W, I0, I1, I2, I3) { unsigned long long e; \
    e = __ldg(&W[I0].x); acc16(s0l, s0h, (unsigned)e, (unsigned)(e >> 32)); \
    e = __ldg(&W[I1].x); acc16(s1l, s1h, (unsigned)e, (unsigned)(e >> 32)); \
    e = __ldg(&W[I2].x); acc16(s2l, s2h, (unsigned)e, (unsigned)(e >> 32)); \
    e = __ldg(&W[I3].x); acc16(s3l, s3h, (unsigned)e, (unsigned)(e >> 32)); }
    PASSH(g_Tt, iT0, iT1, iT2, iT3)
    PASSH(g_Bb, iB0, iB1, iB2, iB3)
#undef PASSH

    // horizontal hi-half via shuffle: pixel p's r2 comes from lane tx-3
    unsigned a0 = __shfl_up_sync(0xFFFFFFFFu, gh.z, 3);
    unsigned a1 = __shfl_up_sync(0xFFFFFFFFu, gh.w, 3);
    if (tx < 3) { const uint4 t = __ldg(&g_Hh[wl]); a0 = t.z; a1 = t.w; }

    // slot writes: dest pixel coords
    sl[0][ty + 3][tx]     = make_uint2(gv.z, gv.w);   // vert  -> (ty+3, tx)
    sl[1][ty + 3][tx + 3] = make_uint2(gd.z, gd.w);   // diag  -> (ty+3, tx+3)
    sl[2][ty + 3][tx]     = make_uint2(ga.z, ga.w);   // anti  -> (ty+3, tx-3), x stored +3
    __syncthreads();

    const uint2 rB0 = sl[0][ty][tx];
    const uint2 rC0 = sl[1][ty][tx];
    const uint2 rD0 = sl[2][ty][tx + 3];
    const uint2 rB = (ty >= 3)             ? rB0 : fB;
    const uint2 rC = (ty >= 3 && tx >= 3)  ? rC0 : fC;
    const uint2 rD = (ty >= 3 && tx <= 28) ? rD0 : fD;

    // accumulate merged (fp16) contributions
    acc16(s0l, s0h, gh.x, gh.y);   // h r0
    acc16(s1l, s1h, gv.x, gv.y);   // h r1
    acc16(s2l, s2h, a0,   a1);     // h r2
    acc16(s3l, s3h, rB.x, rB.y);   // h r3
    acc16(s0l, s0h, gd.x, gd.y);   // d r0
    acc16(s1l, s1h, ga.x, ga.y);   // d r1
    acc16(s2l, s2h, rC.x, rC.y);   // d r2
    acc16(s3l, s3h, rD.x, rD.y);   // d r3

    const float S0x = lo32(s0l), S0y = hi32(s0l), S0z = lo32(s0h), S0w = hi32(s0h);
    const float S1x = lo32(s1l), S1y = hi32(s1l), S1z = lo32(s1h), S1w = hi32(s1h);
    const float S2x = lo32(s2l), S2y = hi32(s2l), S2z = lo32(s2h), S2w = hi32(s2h);
    const float S3x = lo32(s3l), S3y = hi32(s3l), S3z = lo32(s3h), S3w = hi32(s3h);

    const float a00 = (S0x + S1z + S2w + S3y) * 0.25f;
    const float a01 = (S0y + S1x + S2z + S3w) * 0.25f;
    const float a10 = (S0z + S1w + S2y + S3x) * 0.25f;
    const float a11 = (S0w + S1y + S2x + S3z) * 0.25f;

    float* ob = out + (size_t)blockIdx.z * ((size_t)OW * OW)
                    + (size_t)(2 * (y0 + ty)) * OW + 2 * (x0 + tx);
    stcs2(ob,      a00, a01);
    stcs2(ob + OW, a10, a11);
}

extern "C" void kernel_launch(void* const* d_in, const int* in_sizes, int n_in,
                              void* d_out, int out_size) {
    (void)n_in; (void)out_size;
    const int* img = (const int*)d_in[0];
    const int B = in_sizes[0] / (NN * NN);
    prep_kernel<<<256, 256>>>((const float4*)d_in[1], (const float4*)d_in[2],
                              (const float4*)d_in[3], (const float4*)d_in[4]);
    dim3 blk(TX, TY, 1);
    dim3 grd(NN / TX, NN / TY, B);
    lut4_kernel<<<grd, blk>>>(img, (float*)d_out);
}